// round 6
// baseline (speedup 1.0000x reference)
#include <cuda_runtime.h>
#include <cuda_bf16.h>
#include <cstdint>

// ---------------- problem constants ----------------
#define NN   10000
#define DIN  1716
#define DE1  2000
#define DE2  256
#define DZ   128
#define NE   100000
#define NP   200000
#define MP   10112      // NN padded to 128

#define KP_X    1728
#define KP_2000 2048
#define KP_256  256
#define KP_128  128
#define NP_2000 2048
#define NP_1716 1792
#define NP_256  256
#define NP_128  128

// output layout
#define OFF_EMB1  0ull
#define OFF_BETA  1280000ull
#define OFF_XBAR  1300000ull
#define OFF_PAIRS 18460000ull
#define OFF_LAB   44060000ull

// ---------------- fp32 scratch ----------------
__device__ float g_tra1[NN * DE1];
__device__ float g_tra2[NN * DE2];
__device__ float g_z   [NN * DZ ];
__device__ float g_s1  [NN * DE1];
__device__ float g_s2  [NN * DE2];
__device__ float g_s3  [NN * DZ ];
__device__ float g_h3  [NN * DZ ];
__device__ float g_emb1[NN * DZ ];
__device__ int   g_rowptr[NN + 1];

// ---------------- bf16 split scratch ----------------
__device__ __nv_bfloat16 g_xh [(size_t)MP * KP_X];
__device__ __nv_bfloat16 g_xl [(size_t)MP * KP_X];
__device__ __nv_bfloat16 g_t1h[(size_t)MP * KP_2000];
__device__ __nv_bfloat16 g_t1l[(size_t)MP * KP_2000];
__device__ __nv_bfloat16 g_m1h[(size_t)MP * KP_2000];
__device__ __nv_bfloat16 g_m1l[(size_t)MP * KP_2000];
__device__ __nv_bfloat16 g_t2h[(size_t)MP * KP_256];
__device__ __nv_bfloat16 g_t2l[(size_t)MP * KP_256];
__device__ __nv_bfloat16 g_m2h[(size_t)MP * KP_256];
__device__ __nv_bfloat16 g_m2l[(size_t)MP * KP_256];
__device__ __nv_bfloat16 g_zsh[(size_t)MP * KP_128];
__device__ __nv_bfloat16 g_zsl[(size_t)MP * KP_128];
__device__ __nv_bfloat16 g_d1h[(size_t)MP * KP_256];
__device__ __nv_bfloat16 g_d1l[(size_t)MP * KP_256];
__device__ __nv_bfloat16 g_d2h[(size_t)MP * KP_2000];
__device__ __nv_bfloat16 g_d2l[(size_t)MP * KP_2000];
__device__ __nv_bfloat16 g_bth[(size_t)2048 * 2048];
__device__ __nv_bfloat16 g_btl[(size_t)2048 * 2048];

// ---------------- PTX helpers (compute_100-generic) ----------------
__device__ __forceinline__ uint32_t smem_u32(const void* p) {
    uint32_t a;
    asm("{ .reg .u64 t; cvta.to.shared.u64 t, %1; cvt.u32.u64 %0, t; }" : "=r"(a) : "l"(p));
    return a;
}
#define CP_ASYNC16(dst, src) \
    asm volatile("cp.async.cg.shared.global [%0], [%1], 16;" :: "r"(dst), "l"(src) : "memory")
#define CP_COMMIT() asm volatile("cp.async.commit_group;" ::: "memory")

__device__ __forceinline__ void mma_bf16(float* c, const uint32_t* a, uint32_t b0, uint32_t b1) {
    asm volatile(
        "mma.sync.aligned.m16n8k16.row.col.f32.bf16.bf16.f32 "
        "{%0,%1,%2,%3}, {%4,%5,%6,%7}, {%8,%9}, {%0,%1,%2,%3};"
        : "+f"(c[0]), "+f"(c[1]), "+f"(c[2]), "+f"(c[3])
        : "r"(a[0]), "r"(a[1]), "r"(a[2]), "r"(a[3]), "r"(b0), "r"(b1));
}

// ---------------- bf16-split HMMA GEMM, warp tile 64x64 ----------------
// CTA tile 128x128, 128 threads (4 warps as 2x2 of 64x64 warp tiles).
#define SROW    80
#define TILE_B  (128 * SROW)         // 10240 B
#define STAGE_B (4 * TILE_B)         // 40960 B
#define DSMEM_BYTES (2 * STAGE_B)    // 81920 B

template <bool RELU, bool BIAS>
__global__ void __launch_bounds__(128, 2)
hmma_gemm(int Mreal, int Nreal, int Kp, int ldC, int Npad,
          const __nv_bfloat16* __restrict__ Ah, const __nv_bfloat16* __restrict__ Al,
          const __nv_bfloat16* __restrict__ Bh, const __nv_bfloat16* __restrict__ Bl,
          const float* __restrict__ bias, float* __restrict__ Cf,
          __nv_bfloat16* __restrict__ Sh, __nv_bfloat16* __restrict__ Sl)
{
    extern __shared__ char dsm[];
    const uint32_t sbase = smem_u32(dsm);

    const int tid  = threadIdx.x;
    const int wid  = tid >> 5;
    const int lane = tid & 31;
    const int Arow0 = blockIdx.y * 128;
    const int Brow0 = blockIdx.x * 128;

    // warp layout: 2x2 of 64x64
    const int m0 = (wid & 1) * 64;
    const int n0 = (wid >> 1) * 64;
    const int l4 = lane >> 2;        // 0..7
    const int l2 = (lane & 3) * 2;   // 0,2,4,6

    // loader: each of 128 threads owns one 64B row per tile
    const size_t gA = (size_t)(Arow0 + tid) * Kp;
    const size_t gB = (size_t)(Brow0 + tid) * Kp;

    float acc[4][8][4];
#pragma unroll
    for (int mt = 0; mt < 4; mt++)
#pragma unroll
        for (int nt = 0; nt < 8; nt++)
#pragma unroll
            for (int i = 0; i < 4; i++) acc[mt][nt][i] = 0.f;

    const int nk = Kp >> 5;

    auto load_stage = [&](int s, int k0) {
        const uint32_t st = sbase + s * STAGE_B + tid * SROW;
#pragma unroll
        for (int seg = 0; seg < 4; seg++) {
            const uint32_t d = st + seg * 16;
            const size_t   g = (size_t)k0 + seg * 8;
            CP_ASYNC16(d,              Ah + gA + g);
            CP_ASYNC16(d + TILE_B,     Al + gA + g);
            CP_ASYNC16(d + 2 * TILE_B, Bh + gB + g);
            CP_ASYNC16(d + 3 * TILE_B, Bl + gB + g);
        }
    };

    load_stage(0, 0);
    CP_COMMIT();

    for (int c0 = 0; c0 < nk; c0++) {
        const int s = c0 & 1;
        if (c0 + 1 < nk) {
            load_stage(s ^ 1, (c0 + 1) << 5);
            CP_COMMIT();
            asm volatile("cp.async.wait_group 1;" ::: "memory");
        } else {
            asm volatile("cp.async.wait_group 0;" ::: "memory");
        }
        __syncthreads();

        const char* sb   = dsm + s * STAGE_B;
        const char* As_h = sb;
        const char* As_l = sb + TILE_B;
        const char* Bs_h = sb + 2 * TILE_B;
        const char* Bs_l = sb + 3 * TILE_B;

#pragma unroll
        for (int kk = 0; kk < 32; kk += 16) {
            const int ca = (kk + l2) * 2;
            uint32_t Afh[4][4], Afl[4][4];
#pragma unroll
            for (int mt = 0; mt < 4; mt++) {
                const int r = m0 + mt * 16 + l4;
                Afh[mt][0] = *(const uint32_t*)(As_h + r * SROW + ca);
                Afh[mt][1] = *(const uint32_t*)(As_h + (r + 8) * SROW + ca);
                Afh[mt][2] = *(const uint32_t*)(As_h + r * SROW + ca + 16);
                Afh[mt][3] = *(const uint32_t*)(As_h + (r + 8) * SROW + ca + 16);
                Afl[mt][0] = *(const uint32_t*)(As_l + r * SROW + ca);
                Afl[mt][1] = *(const uint32_t*)(As_l + (r + 8) * SROW + ca);
                Afl[mt][2] = *(const uint32_t*)(As_l + r * SROW + ca + 16);
                Afl[mt][3] = *(const uint32_t*)(As_l + (r + 8) * SROW + ca + 16);
            }
#pragma unroll
            for (int nt = 0; nt < 8; nt++) {
                const int n = n0 + nt * 8 + l4;
                const uint32_t bh0 = *(const uint32_t*)(Bs_h + n * SROW + ca);
                const uint32_t bh1 = *(const uint32_t*)(Bs_h + n * SROW + ca + 16);
                const uint32_t bl0 = *(const uint32_t*)(Bs_l + n * SROW + ca);
                const uint32_t bl1 = *(const uint32_t*)(Bs_l + n * SROW + ca + 16);
#pragma unroll
                for (int mt = 0; mt < 4; mt++) {
                    mma_bf16(acc[mt][nt], Afh[mt], bh0, bh1);
                    mma_bf16(acc[mt][nt], Afh[mt], bl0, bl1);
                    mma_bf16(acc[mt][nt], Afl[mt], bh0, bh1);
                }
            }
        }
        __syncthreads();
    }

    // ---- epilogue: fp32 C (valid region) + optional bf16 hi/lo split (padded) ----
#pragma unroll
    for (int mt = 0; mt < 4; mt++) {
#pragma unroll
        for (int half = 0; half < 2; half++) {
            const int rr = Arow0 + m0 + mt * 16 + l4 + half * 8;
            const bool rok = rr < Mreal;
#pragma unroll
            for (int nt = 0; nt < 8; nt++) {
#pragma unroll
                for (int j = 0; j < 2; j++) {
                    const int col = Brow0 + n0 + nt * 8 + l2 + j;
                    float v = 0.f;
                    if (rok && col < Nreal) {
                        v = acc[mt][nt][half * 2 + j];
                        if (BIAS) v += bias[col];
                        if (RELU) v = fmaxf(v, 0.f);
                        if (Cf) Cf[(size_t)rr * ldC + col] = v;
                    }
                    if (Sh) {
                        __nv_bfloat16 h = __float2bfloat16(v);
                        const size_t so = (size_t)rr * Npad + col;
                        Sh[so] = h;
                        Sl[so] = __float2bfloat16(v - __bfloat162float(h));
                    }
                }
            }
        }
    }
}

// ---------------- x split ----------------
__global__ void split_kernel(const float* __restrict__ A, int M, int K, int Kp,
                             __nv_bfloat16* __restrict__ hi, __nv_bfloat16* __restrict__ lo)
{
    size_t idx = (size_t)blockIdx.x * blockDim.x + threadIdx.x;
    size_t total = (size_t)MP * Kp;
    if (idx >= total) return;
    int r = (int)(idx / Kp), c = (int)(idx % Kp);
    float v = (r < M && c < K) ? A[(size_t)r * K + c] : 0.f;
    __nv_bfloat16 h = __float2bfloat16(v);
    hi[idx] = h;
    lo[idx] = __float2bfloat16(v - __bfloat162float(h));
}

// ---------------- W [K,N] fp32 -> Bt [Np,Kp] bf16 hi/lo ----------------
__global__ void tsplit_kernel(const float* __restrict__ W, int K, int N, int Kp, int Np,
                              __nv_bfloat16* __restrict__ hi, __nv_bfloat16* __restrict__ lo)
{
    size_t idx = (size_t)blockIdx.x * blockDim.x + threadIdx.x;
    size_t total = (size_t)Np * Kp;
    if (idx >= total) return;
    int n = (int)(idx / Kp), k = (int)(idx % Kp);
    float v = (k < K && n < N) ? W[(size_t)k * N + n] : 0.f;
    __nv_bfloat16 h = __float2bfloat16(v);
    hi[idx] = h;
    lo[idx] = __float2bfloat16(v - __bfloat162float(h));
}

// ---------------- sorted-COO -> row_ptr ----------------
__global__ void build_rowptr_kernel(const int* __restrict__ rows)
{
    int r = blockIdx.x * blockDim.x + threadIdx.x;
    if (r > NN) return;
    int lo = 0, hi = NE;
    while (lo < hi) { int m = (lo + hi) >> 1; if (rows[m] < r) lo = m + 1; else hi = m; }
    g_rowptr[r] = lo;
}

// ---------------- SpMM + relu + mix + split (layers 1,2) ----------------
__global__ void spmm_mix_split_kernel(const int* __restrict__ cols, const float* __restrict__ vals,
                                      const float* __restrict__ sup, const float* __restrict__ tra,
                                      int Creal, int Cpad,
                                      __nv_bfloat16* __restrict__ Sh, __nv_bfloat16* __restrict__ Sl)
{
    int r = blockIdx.y;
    int c = blockIdx.x * blockDim.x + threadIdx.x;
    if (c >= Cpad) return;
    float v = 0.f;
    if (r < NN && c < Creal) {
        float acc = 0.f;
        int e0 = g_rowptr[r], e1 = g_rowptr[r + 1];
        for (int e = e0; e < e1; e++)
            acc += vals[e] * sup[(size_t)cols[e] * Creal + c];
        v = 0.5f * (fmaxf(acc, 0.f) + tra[(size_t)r * Creal + c]);
    }
    __nv_bfloat16 h = __float2bfloat16(v);
    const size_t so = (size_t)r * Cpad + c;
    Sh[so] = h;
    Sl[so] = __float2bfloat16(v - __bfloat162float(h));
}

// ---------------- SpMM + relu (layer 3, fp32 out) ----------------
__global__ void spmm_relu_kernel(const int* __restrict__ cols, const float* __restrict__ vals,
                                 const float* __restrict__ sup, int C, float* __restrict__ out)
{
    int r = blockIdx.y;
    int c = blockIdx.x * blockDim.x + threadIdx.x;
    if (c >= C) return;
    float acc = 0.f;
    int e0 = g_rowptr[r], e1 = g_rowptr[r + 1];
    for (int e = e0; e < e1; e++)
        acc += vals[e] * sup[(size_t)cols[e] * C + c];
    out[(size_t)r * C + c] = fmaxf(acc, 0.f);
}

// ---------------- attention fusion ----------------
__global__ void __launch_bounds__(128)
attention_kernel(const float* __restrict__ Wa1, const float* __restrict__ ba1,
                 const float* __restrict__ Wa2, float* __restrict__ out)
{
    int i = blockIdx.x, t = threadIdx.x;
    __shared__ float h3s[DZ], zs[DZ], red0[DZ], red1[DZ];
    __shared__ float b0s, b1s;
    h3s[t] = g_h3[(size_t)i * DZ + t];
    zs[t]  = g_z [(size_t)i * DZ + t];
    __syncthreads();
    float s0 = ba1[t], s1 = ba1[t];
    for (int k = 0; k < DZ; k++) {
        float w = Wa1[k * DZ + t];
        s0 += h3s[k] * w; s1 += zs[k] * w;
    }
    float wa2 = Wa2[t];
    red0[t] = tanhf(s0) * wa2;
    red1[t] = tanhf(s1) * wa2;
    __syncthreads();
    for (int s = 64; s > 0; s >>= 1) {
        if (t < s) { red0[t] += red0[t + s]; red1[t] += red1[t + s]; }
        __syncthreads();
    }
    if (t == 0) {
        float w0 = red0[0], w1 = red1[0];
        float m = fmaxf(w0, w1);
        float e0 = expf(w0 - m), e1 = expf(w1 - m);
        float inv = 1.f / (e0 + e1);
        b0s = e0 * inv; b1s = e1 * inv;
        out[OFF_BETA + (size_t)i * 2 + 0] = b0s;
        out[OFF_BETA + (size_t)i * 2 + 1] = b1s;
    }
    __syncthreads();
    float e = b0s * h3s[t] + b1s * zs[t];
    g_emb1[(size_t)i * DZ + t] = e;
    out[OFF_EMB1 + (size_t)i * DZ + t] = e;
}

__global__ void pairs_kernel(const int* __restrict__ pair_idx, float* __restrict__ out)
{
    long long idx = (long long)blockIdx.x * blockDim.x + threadIdx.x;
    if (idx >= (long long)NP * DZ) return;
    int p = (int)(idx >> 7), c = (int)(idx & 127);
    int a = pair_idx[2 * p], b = pair_idx[2 * p + 1];
    out[OFF_PAIRS + idx] = 0.5f * (g_emb1[(size_t)a * DZ + c] + g_emb1[(size_t)b * DZ + c]);
}

__global__ void labels_kernel(const int* __restrict__ labels, float* __restrict__ out)
{
    int p = blockIdx.x * blockDim.x + threadIdx.x;
    if (p >= NP) return;
    out[OFF_LAB + p] = (float)labels[p];
}

// ---------------- host helpers ----------------
static inline unsigned nblk(size_t n) { return (unsigned)((n + 255) / 256); }

template <bool RELU, bool BIAS>
static void launch_gemm(int Mreal, int Nreal, int Kp, int Npad, int ldC,
                        const __nv_bfloat16* Ah, const __nv_bfloat16* Al,
                        const __nv_bfloat16* Bh, const __nv_bfloat16* Bl,
                        const float* bias, float* Cf,
                        __nv_bfloat16* Sh, __nv_bfloat16* Sl)
{
    cudaFuncSetAttribute(hmma_gemm<RELU, BIAS>,
                         cudaFuncAttributeMaxDynamicSharedMemorySize, DSMEM_BYTES);
    dim3 grid(Npad / 128, MP / 128);
    hmma_gemm<RELU, BIAS><<<grid, 128, DSMEM_BYTES>>>(Mreal, Nreal, Kp, ldC, Npad,
                                                      Ah, Al, Bh, Bl, bias, Cf, Sh, Sl);
}

extern "C" void kernel_launch(void* const* d_in, const int* in_sizes, int n_in,
                              void* d_out, int out_size)
{
    const float* x        = (const float*)d_in[0];
    const int*   adj_rows = (const int*)  d_in[1];
    const int*   adj_cols = (const int*)  d_in[2];
    const float* adj_vals = (const float*)d_in[3];
    const int*   pair_idx = (const int*)  d_in[4];
    const int*   labels   = (const int*)  d_in[5];
    const float* W_enc1 = (const float*)d_in[6];
    const float* b_enc1 = (const float*)d_in[7];
    const float* W_enc2 = (const float*)d_in[8];
    const float* b_enc2 = (const float*)d_in[9];
    const float* W_z    = (const float*)d_in[10];
    const float* b_z    = (const float*)d_in[11];
    const float* W_dec1 = (const float*)d_in[12];
    const float* b_dec1 = (const float*)d_in[13];
    const float* W_dec2 = (const float*)d_in[14];
    const float* b_dec2 = (const float*)d_in[15];
    const float* W_xbar = (const float*)d_in[16];
    const float* b_xbar = (const float*)d_in[17];
    const float* W_g1   = (const float*)d_in[18];
    const float* W_g2   = (const float*)d_in[19];
    const float* W_g3   = (const float*)d_in[20];
    const float* W_a1   = (const float*)d_in[21];
    const float* b_a1   = (const float*)d_in[22];
    const float* W_a2   = (const float*)d_in[23];
    float* out = (float*)d_out;

    float *tra1, *tra2, *z, *s1, *s2, *s3, *h3;
    __nv_bfloat16 *xh, *xl, *t1h, *t1l, *m1h, *m1l, *t2h, *t2l, *m2h, *m2l;
    __nv_bfloat16 *zsh, *zsl, *d1h, *d1l, *d2h, *d2l, *bth, *btl;
    cudaGetSymbolAddress((void**)&tra1, g_tra1);
    cudaGetSymbolAddress((void**)&tra2, g_tra2);
    cudaGetSymbolAddress((void**)&z,    g_z);
    cudaGetSymbolAddress((void**)&s1,   g_s1);
    cudaGetSymbolAddress((void**)&s2,   g_s2);
    cudaGetSymbolAddress((void**)&s3,   g_s3);
    cudaGetSymbolAddress((void**)&h3,   g_h3);
    cudaGetSymbolAddress((void**)&xh,  g_xh);
    cudaGetSymbolAddress((void**)&xl,  g_xl);
    cudaGetSymbolAddress((void**)&t1h, g_t1h);
    cudaGetSymbolAddress((void**)&t1l, g_t1l);
    cudaGetSymbolAddress((void**)&m1h, g_m1h);
    cudaGetSymbolAddress((void**)&m1l, g_m1l);
    cudaGetSymbolAddress((void**)&t2h, g_t2h);
    cudaGetSymbolAddress((void**)&t2l, g_t2l);
    cudaGetSymbolAddress((void**)&m2h, g_m2h);
    cudaGetSymbolAddress((void**)&m2l, g_m2l);
    cudaGetSymbolAddress((void**)&zsh, g_zsh);
    cudaGetSymbolAddress((void**)&zsl, g_zsl);
    cudaGetSymbolAddress((void**)&d1h, g_d1h);
    cudaGetSymbolAddress((void**)&d1l, g_d1l);
    cudaGetSymbolAddress((void**)&d2h, g_d2h);
    cudaGetSymbolAddress((void**)&d2l, g_d2l);
    cudaGetSymbolAddress((void**)&bth, g_bth);
    cudaGetSymbolAddress((void**)&btl, g_btl);

    build_rowptr_kernel<<<(NN + 256) / 256, 256>>>(adj_rows);

    // x split (shared by enc1 and g1)
    split_kernel<<<nblk((size_t)MP * KP_X), 256>>>(x, NN, DIN, KP_X, xh, xl);

    // enc1: tra1 = relu(x @ W_enc1 + b); epilogue also emits tra1 split -> t1
    tsplit_kernel<<<nblk((size_t)NP_2000 * KP_X), 256>>>(W_enc1, DIN, DE1, KP_X, NP_2000, bth, btl);
    launch_gemm<true, true>(NN, DE1, KP_X, NP_2000, DE1, xh, xl, bth, btl, b_enc1, tra1, t1h, t1l);

    // g1: s1 = x @ W_g1
    tsplit_kernel<<<nblk((size_t)NP_2000 * KP_X), 256>>>(W_g1, DIN, DE1, KP_X, NP_2000, bth, btl);
    launch_gemm<false, false>(NN, DE1, KP_X, NP_2000, DE1, xh, xl, bth, btl, nullptr, s1, nullptr, nullptr);

    // spmm1 -> mix(h1,tra1) split -> m1
    spmm_mix_split_kernel<<<dim3((KP_2000 + 255) / 256, MP), 256>>>(adj_cols, adj_vals, s1, tra1, DE1, KP_2000, m1h, m1l);

    // enc2: tra2 = relu(tra1 @ W_enc2 + b); epilogue split -> t2
    tsplit_kernel<<<nblk((size_t)NP_256 * KP_2000), 256>>>(W_enc2, DE1, DE2, KP_2000, NP_256, bth, btl);
    launch_gemm<true, true>(NN, DE2, KP_2000, NP_256, DE2, t1h, t1l, bth, btl, b_enc2, tra2, t2h, t2l);

    // z = tra2 @ W_z + b; epilogue split -> zs
    tsplit_kernel<<<nblk((size_t)NP_128 * KP_256), 256>>>(W_z, DE2, DZ, KP_256, NP_128, bth, btl);
    launch_gemm<false, true>(NN, DZ, KP_256, NP_128, DZ, t2h, t2l, bth, btl, b_z, z, zsh, zsl);

    // dec1 = relu(z @ W_dec1 + b); split only -> d1
    tsplit_kernel<<<nblk((size_t)NP_256 * KP_128), 256>>>(W_dec1, DZ, DE2, KP_128, NP_256, bth, btl);
    launch_gemm<true, true>(NN, DE2, KP_128, NP_256, DE2, zsh, zsl, bth, btl, b_dec1, nullptr, d1h, d1l);

    // dec2 = relu(dec1 @ W_dec2 + b); split only -> d2
    tsplit_kernel<<<nblk((size_t)NP_2000 * KP_256), 256>>>(W_dec2, DE2, DE1, KP_256, NP_2000, bth, btl);
    launch_gemm<true, true>(NN, DE1, KP_256, NP_2000, DE1, d1h, d1l, bth, btl, b_dec2, nullptr, d2h, d2l);

    // x_bar = dec2 @ W_xbar + b  (fp32 direct to output)
    tsplit_kernel<<<nblk((size_t)NP_1716 * KP_2000), 256>>>(W_xbar, DE1, DIN, KP_2000, NP_1716, bth, btl);
    launch_gemm<false, true>(NN, DIN, KP_2000, NP_1716, DIN, d2h, d2l, bth, btl, b_xbar, out + OFF_XBAR, nullptr, nullptr);

    // g2: s2 = mix1 @ W_g2
    tsplit_kernel<<<nblk((size_t)NP_256 * KP_2000), 256>>>(W_g2, DE1, DE2, KP_2000, NP_256, bth, btl);
    launch_gemm<false, false>(NN, DE2, KP_2000, NP_256, DE2, m1h, m1l, bth, btl, nullptr, s2, nullptr, nullptr);

    // spmm2 -> mix(h2,tra2) split -> m2
    spmm_mix_split_kernel<<<dim3((KP_256 + 255) / 256, MP), 256>>>(adj_cols, adj_vals, s2, tra2, DE2, KP_256, m2h, m2l);

    // g3: s3 = mix2 @ W_g3
    tsplit_kernel<<<nblk((size_t)NP_128 * KP_256), 256>>>(W_g3, DE2, DZ, KP_256, NP_128, bth, btl);
    launch_gemm<false, false>(NN, DZ, KP_256, NP_128, DZ, m2h, m2l, bth, btl, nullptr, s3, nullptr, nullptr);

    // spmm3 -> h3 fp32
    spmm_relu_kernel<<<dim3((DZ + 255) / 256, NN), 256>>>(adj_cols, adj_vals, s3, DZ, h3);

    // attention fusion + outputs
    attention_kernel<<<NN, 128>>>(W_a1, b_a1, W_a2, out);
    pairs_kernel<<<nblk((size_t)NP * DZ), 256>>>(pair_idx, out);
    labels_kernel<<<(NP + 255) / 256, 256>>>(labels, out);
}

// round 7
// speedup vs baseline: 1.3191x; 1.3191x over previous
#include <cuda_runtime.h>
#include <cuda_bf16.h>
#include <cstdint>

// ---------------- problem constants ----------------
#define NN   10000
#define DIN  1716
#define DE1  2000
#define DE2  256
#define DZ   128
#define NE   100000
#define NP   200000
#define MP   10112      // NN padded to 128

#define KP_X    1728
#define KP_2000 2048
#define KP_256  256
#define KP_128  128
#define NP_2000 2048
#define NP_1716 1792
#define NP_256  256
#define NP_128  128

// output layout
#define OFF_EMB1  0ull
#define OFF_BETA  1280000ull
#define OFF_XBAR  1300000ull
#define OFF_PAIRS 18460000ull
#define OFF_LAB   44060000ull

// ---------------- fp32 scratch ----------------
__device__ float g_tra1[NN * DE1];
__device__ float g_tra2[NN * DE2];
__device__ float g_z   [NN * DZ ];
__device__ float g_s1  [NN * DE1];
__device__ float g_s2  [NN * DE2];
__device__ float g_s3  [NN * DZ ];
__device__ float g_h3  [NN * DZ ];
__device__ float g_emb1[NN * DZ ];
__device__ int   g_rowptr[NN + 1];

// ---------------- bf16 split scratch ----------------
__device__ __nv_bfloat16 g_xh [(size_t)MP * KP_X];
__device__ __nv_bfloat16 g_xl [(size_t)MP * KP_X];
__device__ __nv_bfloat16 g_t1h[(size_t)MP * KP_2000];
__device__ __nv_bfloat16 g_t1l[(size_t)MP * KP_2000];
__device__ __nv_bfloat16 g_m1h[(size_t)MP * KP_2000];
__device__ __nv_bfloat16 g_m1l[(size_t)MP * KP_2000];
__device__ __nv_bfloat16 g_t2h[(size_t)MP * KP_256];
__device__ __nv_bfloat16 g_t2l[(size_t)MP * KP_256];
__device__ __nv_bfloat16 g_m2h[(size_t)MP * KP_256];
__device__ __nv_bfloat16 g_m2l[(size_t)MP * KP_256];
__device__ __nv_bfloat16 g_zsh[(size_t)MP * KP_128];
__device__ __nv_bfloat16 g_zsl[(size_t)MP * KP_128];
__device__ __nv_bfloat16 g_d1h[(size_t)MP * KP_256];
__device__ __nv_bfloat16 g_d1l[(size_t)MP * KP_256];
__device__ __nv_bfloat16 g_d2h[(size_t)MP * KP_2000];
__device__ __nv_bfloat16 g_d2l[(size_t)MP * KP_2000];
__device__ __nv_bfloat16 g_bth[(size_t)2048 * 2048];
__device__ __nv_bfloat16 g_btl[(size_t)2048 * 2048];

// ---------------- PTX helpers (compute_100-generic) ----------------
__device__ __forceinline__ uint32_t smem_u32(const void* p) {
    uint32_t a;
    asm("{ .reg .u64 t; cvta.to.shared.u64 t, %1; cvt.u32.u64 %0, t; }" : "=r"(a) : "l"(p));
    return a;
}
#define CP_ASYNC16(dst, src) \
    asm volatile("cp.async.cg.shared.global [%0], [%1], 16;" :: "r"(dst), "l"(src) : "memory")
#define CP_COMMIT() asm volatile("cp.async.commit_group;" ::: "memory")

#define LDSM_X4(d0, d1, d2, d3, addr) \
    asm volatile("ldmatrix.sync.aligned.m8n8.x4.shared.b16 {%0,%1,%2,%3}, [%4];" \
        : "=r"(d0), "=r"(d1), "=r"(d2), "=r"(d3) : "r"(addr))

__device__ __forceinline__ void mma_bf16(float* c, const uint32_t* a, uint32_t b0, uint32_t b1) {
    asm volatile(
        "mma.sync.aligned.m16n8k16.row.col.f32.bf16.bf16.f32 "
        "{%0,%1,%2,%3}, {%4,%5,%6,%7}, {%8,%9}, {%0,%1,%2,%3};"
        : "+f"(c[0]), "+f"(c[1]), "+f"(c[2]), "+f"(c[3])
        : "r"(a[0]), "r"(a[1]), "r"(a[2]), "r"(a[3]), "r"(b0), "r"(b1));
}

// ---------------- bf16-split HMMA GEMM (R5 geometry + ldmatrix) ----------------
// CTA tile 128x128, 256 threads, 8 warps of 32x64. 2-stage cp.async.
#define SROW    80
#define TILE_B  (128 * SROW)
#define STAGE_B (4 * TILE_B)
#define DSMEM_BYTES (2 * STAGE_B)    // 81920 B

template <bool RELU, bool BIAS>
__global__ void __launch_bounds__(256, 2)
hmma_gemm(int Mreal, int Nreal, int Kp, int ldC, int Npad,
          const __nv_bfloat16* __restrict__ Ah, const __nv_bfloat16* __restrict__ Al,
          const __nv_bfloat16* __restrict__ Bh, const __nv_bfloat16* __restrict__ Bl,
          const float* __restrict__ bias, float* __restrict__ Cf,
          __nv_bfloat16* __restrict__ Sh, __nv_bfloat16* __restrict__ Sl)
{
    extern __shared__ char dsm[];
    const uint32_t sbase = smem_u32(dsm);

    const int tid  = threadIdx.x;
    const int wid  = tid >> 5;
    const int lane = tid & 31;
    const int Arow0 = blockIdx.y * 128;
    const int Brow0 = blockIdx.x * 128;

    const int lrow = tid >> 1;
    const int lseg = (tid & 1) * 2;
    const size_t gA = (size_t)(Arow0 + lrow) * Kp;
    const size_t gB = (size_t)(Brow0 + lrow) * Kp;

    const int m0 = (wid & 3) * 32;
    const int n0 = (wid >> 2) * 64;
    const int l4 = lane >> 2;
    const int l2 = (lane & 3) * 2;

    // ldmatrix per-lane address components (byte offsets within a tile)
    //  A x4: lanes 0-15 -> row (m0+mt*16+lane), col kk; lanes 16-31 -> row lane-16, col kk+8
    const uint32_t aoffs = (uint32_t)((m0 + (lane & 15)) * SROW + ((lane >> 4) << 4));
    //  B x4: matrices = {n 0-7 @kk, n 0-7 @kk+8, n 8-15 @kk, n 8-15 @kk+8}
    const uint32_t boffs = (uint32_t)((n0 + (lane & 7) + ((lane >> 4) << 3)) * SROW
                                      + (((lane >> 3) & 1) << 4));

    float acc[2][8][4];
#pragma unroll
    for (int mt = 0; mt < 2; mt++)
#pragma unroll
        for (int nt = 0; nt < 8; nt++)
#pragma unroll
            for (int i = 0; i < 4; i++) acc[mt][nt][i] = 0.f;

    const int nk = Kp >> 5;

    auto load_stage = [&](int s, int k0) {
        const uint32_t st = sbase + s * STAGE_B + lrow * SROW + lseg * 16;
        const size_t goff = (size_t)k0 + lseg * 8;
#pragma unroll
        for (int seg = 0; seg < 2; seg++) {
            const uint32_t d = st + seg * 16;
            const size_t   g = goff + seg * 8;
            CP_ASYNC16(d,              Ah + gA + g);
            CP_ASYNC16(d + TILE_B,     Al + gA + g);
            CP_ASYNC16(d + 2 * TILE_B, Bh + gB + g);
            CP_ASYNC16(d + 3 * TILE_B, Bl + gB + g);
        }
    };

    load_stage(0, 0);
    CP_COMMIT();

    for (int c0 = 0; c0 < nk; c0++) {
        const int s = c0 & 1;
        if (c0 + 1 < nk) {
            load_stage(s ^ 1, (c0 + 1) << 5);
            CP_COMMIT();
            asm volatile("cp.async.wait_group 1;" ::: "memory");
        } else {
            asm volatile("cp.async.wait_group 0;" ::: "memory");
        }
        __syncthreads();

        const uint32_t sb  = sbase + s * STAGE_B;
        const uint32_t sAh = sb + aoffs;
        const uint32_t sAl = sb + TILE_B + aoffs;
        const uint32_t sBh = sb + 2 * TILE_B + boffs;
        const uint32_t sBl = sb + 3 * TILE_B + boffs;

#pragma unroll
        for (int kk = 0; kk < 2; kk++) {
            const uint32_t kb = kk * 32;   // 16 bf16 = 32 bytes per k16 step
            uint32_t Afh[2][4], Afl[2][4];
#pragma unroll
            for (int mt = 0; mt < 2; mt++) {
                LDSM_X4(Afh[mt][0], Afh[mt][1], Afh[mt][2], Afh[mt][3],
                        sAh + mt * (16 * SROW) + kb);
                LDSM_X4(Afl[mt][0], Afl[mt][1], Afl[mt][2], Afl[mt][3],
                        sAl + mt * (16 * SROW) + kb);
            }
#pragma unroll
            for (int ntp = 0; ntp < 4; ntp++) {
                uint32_t bh0, bh1, bh2, bh3, bl0, bl1, bl2, bl3;
                LDSM_X4(bh0, bh1, bh2, bh3, sBh + ntp * (16 * SROW) + kb);
                LDSM_X4(bl0, bl1, bl2, bl3, sBl + ntp * (16 * SROW) + kb);
#pragma unroll
                for (int mt = 0; mt < 2; mt++) {
                    mma_bf16(acc[mt][2 * ntp],     Afh[mt], bh0, bh1);
                    mma_bf16(acc[mt][2 * ntp],     Afh[mt], bl0, bl1);
                    mma_bf16(acc[mt][2 * ntp],     Afl[mt], bh0, bh1);
                    mma_bf16(acc[mt][2 * ntp + 1], Afh[mt], bh2, bh3);
                    mma_bf16(acc[mt][2 * ntp + 1], Afh[mt], bl2, bl3);
                    mma_bf16(acc[mt][2 * ntp + 1], Afl[mt], bh2, bh3);
                }
            }
        }
        __syncthreads();
    }

    // ---- epilogue: fp32 C (valid region) + optional bf16 hi/lo split (padded) ----
#pragma unroll
    for (int mt = 0; mt < 2; mt++) {
#pragma unroll
        for (int half = 0; half < 2; half++) {
            const int rr = Arow0 + m0 + mt * 16 + l4 + half * 8;
            const bool rok = rr < Mreal;
#pragma unroll
            for (int nt = 0; nt < 8; nt++) {
#pragma unroll
                for (int j = 0; j < 2; j++) {
                    const int col = Brow0 + n0 + nt * 8 + l2 + j;
                    float v = 0.f;
                    if (rok && col < Nreal) {
                        v = acc[mt][nt][half * 2 + j];
                        if (BIAS) v += bias[col];
                        if (RELU) v = fmaxf(v, 0.f);
                        if (Cf) Cf[(size_t)rr * ldC + col] = v;
                    }
                    if (Sh) {
                        __nv_bfloat16 h = __float2bfloat16(v);
                        const size_t so = (size_t)rr * Npad + col;
                        Sh[so] = h;
                        Sl[so] = __float2bfloat16(v - __bfloat162float(h));
                    }
                }
            }
        }
    }
}

// ---------------- x split ----------------
__global__ void split_kernel(const float* __restrict__ A, int M, int K, int Kp,
                             __nv_bfloat16* __restrict__ hi, __nv_bfloat16* __restrict__ lo)
{
    size_t idx = (size_t)blockIdx.x * blockDim.x + threadIdx.x;
    size_t total = (size_t)MP * Kp;
    if (idx >= total) return;
    int r = (int)(idx / Kp), c = (int)(idx % Kp);
    float v = (r < M && c < K) ? A[(size_t)r * K + c] : 0.f;
    __nv_bfloat16 h = __float2bfloat16(v);
    hi[idx] = h;
    lo[idx] = __float2bfloat16(v - __bfloat162float(h));
}

// ---------------- W [K,N] fp32 -> Bt [Np,Kp] bf16 hi/lo ----------------
__global__ void tsplit_kernel(const float* __restrict__ W, int K, int N, int Kp, int Np,
                              __nv_bfloat16* __restrict__ hi, __nv_bfloat16* __restrict__ lo)
{
    size_t idx = (size_t)blockIdx.x * blockDim.x + threadIdx.x;
    size_t total = (size_t)Np * Kp;
    if (idx >= total) return;
    int n = (int)(idx / Kp), k = (int)(idx % Kp);
    float v = (k < K && n < N) ? W[(size_t)k * N + n] : 0.f;
    __nv_bfloat16 h = __float2bfloat16(v);
    hi[idx] = h;
    lo[idx] = __float2bfloat16(v - __bfloat162float(h));
}

// ---------------- sorted-COO -> row_ptr ----------------
__global__ void build_rowptr_kernel(const int* __restrict__ rows)
{
    int r = blockIdx.x * blockDim.x + threadIdx.x;
    if (r > NN) return;
    int lo = 0, hi = NE;
    while (lo < hi) { int m = (lo + hi) >> 1; if (rows[m] < r) lo = m + 1; else hi = m; }
    g_rowptr[r] = lo;
}

// ---------------- SpMM + relu + mix + split (layers 1,2) ----------------
__global__ void spmm_mix_split_kernel(const int* __restrict__ cols, const float* __restrict__ vals,
                                      const float* __restrict__ sup, const float* __restrict__ tra,
                                      int Creal, int Cpad,
                                      __nv_bfloat16* __restrict__ Sh, __nv_bfloat16* __restrict__ Sl)
{
    int r = blockIdx.y;
    int c = blockIdx.x * blockDim.x + threadIdx.x;
    if (c >= Cpad) return;
    float v = 0.f;
    if (r < NN && c < Creal) {
        float acc = 0.f;
        int e0 = g_rowptr[r], e1 = g_rowptr[r + 1];
        for (int e = e0; e < e1; e++)
            acc += vals[e] * sup[(size_t)cols[e] * Creal + c];
        v = 0.5f * (fmaxf(acc, 0.f) + tra[(size_t)r * Creal + c]);
    }
    __nv_bfloat16 h = __float2bfloat16(v);
    const size_t so = (size_t)r * Cpad + c;
    Sh[so] = h;
    Sl[so] = __float2bfloat16(v - __bfloat162float(h));
}

// ---------------- SpMM + relu (layer 3, fp32 out) ----------------
__global__ void spmm_relu_kernel(const int* __restrict__ cols, const float* __restrict__ vals,
                                 const float* __restrict__ sup, int C, float* __restrict__ out)
{
    int r = blockIdx.y;
    int c = blockIdx.x * blockDim.x + threadIdx.x;
    if (c >= C) return;
    float acc = 0.f;
    int e0 = g_rowptr[r], e1 = g_rowptr[r + 1];
    for (int e = e0; e < e1; e++)
        acc += vals[e] * sup[(size_t)cols[e] * C + c];
    out[(size_t)r * C + c] = fmaxf(acc, 0.f);
}

// ---------------- attention fusion ----------------
__global__ void __launch_bounds__(128)
attention_kernel(const float* __restrict__ Wa1, const float* __restrict__ ba1,
                 const float* __restrict__ Wa2, float* __restrict__ out)
{
    int i = blockIdx.x, t = threadIdx.x;
    __shared__ float h3s[DZ], zs[DZ], red0[DZ], red1[DZ];
    __shared__ float b0s, b1s;
    h3s[t] = g_h3[(size_t)i * DZ + t];
    zs[t]  = g_z [(size_t)i * DZ + t];
    __syncthreads();
    float s0 = ba1[t], s1 = ba1[t];
    for (int k = 0; k < DZ; k++) {
        float w = Wa1[k * DZ + t];
        s0 += h3s[k] * w; s1 += zs[k] * w;
    }
    float wa2 = Wa2[t];
    red0[t] = tanhf(s0) * wa2;
    red1[t] = tanhf(s1) * wa2;
    __syncthreads();
    for (int s = 64; s > 0; s >>= 1) {
        if (t < s) { red0[t] += red0[t + s]; red1[t] += red1[t + s]; }
        __syncthreads();
    }
    if (t == 0) {
        float w0 = red0[0], w1 = red1[0];
        float m = fmaxf(w0, w1);
        float e0 = expf(w0 - m), e1 = expf(w1 - m);
        float inv = 1.f / (e0 + e1);
        b0s = e0 * inv; b1s = e1 * inv;
        out[OFF_BETA + (size_t)i * 2 + 0] = b0s;
        out[OFF_BETA + (size_t)i * 2 + 1] = b1s;
    }
    __syncthreads();
    float e = b0s * h3s[t] + b1s * zs[t];
    g_emb1[(size_t)i * DZ + t] = e;
    out[OFF_EMB1 + (size_t)i * DZ + t] = e;
}

__global__ void pairs_kernel(const int* __restrict__ pair_idx, float* __restrict__ out)
{
    long long idx = (long long)blockIdx.x * blockDim.x + threadIdx.x;
    if (idx >= (long long)NP * DZ) return;
    int p = (int)(idx >> 7), c = (int)(idx & 127);
    int a = pair_idx[2 * p], b = pair_idx[2 * p + 1];
    out[OFF_PAIRS + idx] = 0.5f * (g_emb1[(size_t)a * DZ + c] + g_emb1[(size_t)b * DZ + c]);
}

__global__ void labels_kernel(const int* __restrict__ labels, float* __restrict__ out)
{
    int p = blockIdx.x * blockDim.x + threadIdx.x;
    if (p >= NP) return;
    out[OFF_LAB + p] = (float)labels[p];
}

// ---------------- host helpers ----------------
static inline unsigned nblk(size_t n) { return (unsigned)((n + 255) / 256); }

template <bool RELU, bool BIAS>
static void launch_gemm(int Mreal, int Nreal, int Kp, int Npad, int ldC,
                        const __nv_bfloat16* Ah, const __nv_bfloat16* Al,
                        const __nv_bfloat16* Bh, const __nv_bfloat16* Bl,
                        const float* bias, float* Cf,
                        __nv_bfloat16* Sh, __nv_bfloat16* Sl)
{
    cudaFuncSetAttribute(hmma_gemm<RELU, BIAS>,
                         cudaFuncAttributeMaxDynamicSharedMemorySize, DSMEM_BYTES);
    dim3 grid(Npad / 128, MP / 128);
    hmma_gemm<RELU, BIAS><<<grid, 256, DSMEM_BYTES>>>(Mreal, Nreal, Kp, ldC, Npad,
                                                      Ah, Al, Bh, Bl, bias, Cf, Sh, Sl);
}

extern "C" void kernel_launch(void* const* d_in, const int* in_sizes, int n_in,
                              void* d_out, int out_size)
{
    const float* x        = (const float*)d_in[0];
    const int*   adj_rows = (const int*)  d_in[1];
    const int*   adj_cols = (const int*)  d_in[2];
    const float* adj_vals = (const float*)d_in[3];
    const int*   pair_idx = (const int*)  d_in[4];
    const int*   labels   = (const int*)  d_in[5];
    const float* W_enc1 = (const float*)d_in[6];
    const float* b_enc1 = (const float*)d_in[7];
    const float* W_enc2 = (const float*)d_in[8];
    const float* b_enc2 = (const float*)d_in[9];
    const float* W_z    = (const float*)d_in[10];
    const float* b_z    = (const float*)d_in[11];
    const float* W_dec1 = (const float*)d_in[12];
    const float* b_dec1 = (const float*)d_in[13];
    const float* W_dec2 = (const float*)d_in[14];
    const float* b_dec2 = (const float*)d_in[15];
    const float* W_xbar = (const float*)d_in[16];
    const float* b_xbar = (const float*)d_in[17];
    const float* W_g1   = (const float*)d_in[18];
    const float* W_g2   = (const float*)d_in[19];
    const float* W_g3   = (const float*)d_in[20];
    const float* W_a1   = (const float*)d_in[21];
    const float* b_a1   = (const float*)d_in[22];
    const float* W_a2   = (const float*)d_in[23];
    float* out = (float*)d_out;

    float *tra1, *tra2, *z, *s1, *s2, *s3, *h3;
    __nv_bfloat16 *xh, *xl, *t1h, *t1l, *m1h, *m1l, *t2h, *t2l, *m2h, *m2l;
    __nv_bfloat16 *zsh, *zsl, *d1h, *d1l, *d2h, *d2l, *bth, *btl;
    cudaGetSymbolAddress((void**)&tra1, g_tra1);
    cudaGetSymbolAddress((void**)&tra2, g_tra2);
    cudaGetSymbolAddress((void**)&z,    g_z);
    cudaGetSymbolAddress((void**)&s1,   g_s1);
    cudaGetSymbolAddress((void**)&s2,   g_s2);
    cudaGetSymbolAddress((void**)&s3,   g_s3);
    cudaGetSymbolAddress((void**)&h3,   g_h3);
    cudaGetSymbolAddress((void**)&xh,  g_xh);
    cudaGetSymbolAddress((void**)&xl,  g_xl);
    cudaGetSymbolAddress((void**)&t1h, g_t1h);
    cudaGetSymbolAddress((void**)&t1l, g_t1l);
    cudaGetSymbolAddress((void**)&m1h, g_m1h);
    cudaGetSymbolAddress((void**)&m1l, g_m1l);
    cudaGetSymbolAddress((void**)&t2h, g_t2h);
    cudaGetSymbolAddress((void**)&t2l, g_t2l);
    cudaGetSymbolAddress((void**)&m2h, g_m2h);
    cudaGetSymbolAddress((void**)&m2l, g_m2l);
    cudaGetSymbolAddress((void**)&zsh, g_zsh);
    cudaGetSymbolAddress((void**)&zsl, g_zsl);
    cudaGetSymbolAddress((void**)&d1h, g_d1h);
    cudaGetSymbolAddress((void**)&d1l, g_d1l);
    cudaGetSymbolAddress((void**)&d2h, g_d2h);
    cudaGetSymbolAddress((void**)&d2l, g_d2l);
    cudaGetSymbolAddress((void**)&bth, g_bth);
    cudaGetSymbolAddress((void**)&btl, g_btl);

    build_rowptr_kernel<<<(NN + 256) / 256, 256>>>(adj_rows);

    // x split (shared by enc1 and g1)
    split_kernel<<<nblk((size_t)MP * KP_X), 256>>>(x, NN, DIN, KP_X, xh, xl);

    // enc1: tra1 = relu(x @ W_enc1 + b); epilogue also emits tra1 split -> t1
    tsplit_kernel<<<nblk((size_t)NP_2000 * KP_X), 256>>>(W_enc1, DIN, DE1, KP_X, NP_2000, bth, btl);
    launch_gemm<true, true>(NN, DE1, KP_X, NP_2000, DE1, xh, xl, bth, btl, b_enc1, tra1, t1h, t1l);

    // g1: s1 = x @ W_g1
    tsplit_kernel<<<nblk((size_t)NP_2000 * KP_X), 256>>>(W_g1, DIN, DE1, KP_X, NP_2000, bth, btl);
    launch_gemm<false, false>(NN, DE1, KP_X, NP_2000, DE1, xh, xl, bth, btl, nullptr, s1, nullptr, nullptr);

    // spmm1 -> mix(h1,tra1) split -> m1
    spmm_mix_split_kernel<<<dim3((KP_2000 + 255) / 256, MP), 256>>>(adj_cols, adj_vals, s1, tra1, DE1, KP_2000, m1h, m1l);

    // enc2: tra2 = relu(tra1 @ W_enc2 + b); epilogue split -> t2
    tsplit_kernel<<<nblk((size_t)NP_256 * KP_2000), 256>>>(W_enc2, DE1, DE2, KP_2000, NP_256, bth, btl);
    launch_gemm<true, true>(NN, DE2, KP_2000, NP_256, DE2, t1h, t1l, bth, btl, b_enc2, tra2, t2h, t2l);

    // z = tra2 @ W_z + b; epilogue split -> zs
    tsplit_kernel<<<nblk((size_t)NP_128 * KP_256), 256>>>(W_z, DE2, DZ, KP_256, NP_128, bth, btl);
    launch_gemm<false, true>(NN, DZ, KP_256, NP_128, DZ, t2h, t2l, bth, btl, b_z, z, zsh, zsl);

    // dec1 = relu(z @ W_dec1 + b); split only -> d1
    tsplit_kernel<<<nblk((size_t)NP_256 * KP_128), 256>>>(W_dec1, DZ, DE2, KP_128, NP_256, bth, btl);
    launch_gemm<true, true>(NN, DE2, KP_128, NP_256, DE2, zsh, zsl, bth, btl, b_dec1, nullptr, d1h, d1l);

    // dec2 = relu(dec1 @ W_dec2 + b); split only -> d2
    tsplit_kernel<<<nblk((size_t)NP_2000 * KP_256), 256>>>(W_dec2, DE2, DE1, KP_256, NP_2000, bth, btl);
    launch_gemm<true, true>(NN, DE1, KP_256, NP_2000, DE1, d1h, d1l, bth, btl, b_dec2, nullptr, d2h, d2l);

    // x_bar = dec2 @ W_xbar + b  (fp32 direct to output)
    tsplit_kernel<<<nblk((size_t)NP_1716 * KP_2000), 256>>>(W_xbar, DE1, DIN, KP_2000, NP_1716, bth, btl);
    launch_gemm<false, true>(NN, DIN, KP_2000, NP_1716, DIN, d2h, d2l, bth, btl, b_xbar, out + OFF_XBAR, nullptr, nullptr);

    // g2: s2 = mix1 @ W_g2
    tsplit_kernel<<<nblk((size_t)NP_256 * KP_2000), 256>>>(W_g2, DE1, DE2, KP_2000, NP_256, bth, btl);
    launch_gemm<false, false>(NN, DE2, KP_2000, NP_256, DE2, m1h, m1l, bth, btl, nullptr, s2, nullptr, nullptr);

    // spmm2 -> mix(h2,tra2) split -> m2
    spmm_mix_split_kernel<<<dim3((KP_256 + 255) / 256, MP), 256>>>(adj_cols, adj_vals, s2, tra2, DE2, KP_256, m2h, m2l);

    // g3: s3 = mix2 @ W_g3
    tsplit_kernel<<<nblk((size_t)NP_128 * KP_256), 256>>>(W_g3, DE2, DZ, KP_256, NP_128, bth, btl);
    launch_gemm<false, false>(NN, DZ, KP_256, NP_128, DZ, m2h, m2l, bth, btl, nullptr, s3, nullptr, nullptr);

    // spmm3 -> h3 fp32
    spmm_relu_kernel<<<dim3((DZ + 255) / 256, NN), 256>>>(adj_cols, adj_vals, s3, DZ, h3);

    // attention fusion + outputs
    attention_kernel<<<NN, 128>>>(W_a1, b_a1, W_a2, out);
    pairs_kernel<<<nblk((size_t)NP * DZ), 256>>>(pair_idx, out);
    labels_kernel<<<(NP + 255) / 256, 256>>>(labels, out);
}